// round 2
// baseline (speedup 1.0000x reference)
#include <cuda_runtime.h>
#include <math.h>

#define NNODES 100000
#define NEDGES 1600000
#define MAXF 256

// Scratch (device globals; allocation-free per harness rules)
__device__ float g_dis[NNODES];
__device__ float g_xw[(size_t)NNODES * MAXF];
__device__ float g_h0[(size_t)NNODES * MAXF];
__device__ float g_h1[(size_t)NNODES * MAXF];
__device__ int   g_rows[NEDGES];
__device__ int   g_cols[NEDGES];
__device__ float g_norm[NEDGES];
__device__ int   g_is64;

// ---------------------------------------------------------------------------
// Edge-index dtype detection + normalization to int32
// ---------------------------------------------------------------------------
__global__ void detect_dtype_kernel(const void* ei_raw, int N) {
    // Interpret as int64: if data is really int32, value = lo | hi<<32 is huge
    // unless hi==0 (prob ~1e-5 per entry for random indices). Check 8.
    const long long* p = (const long long*)ei_raw;
    int ok = 1;
    for (int i = 0; i < 8; i++) {
        long long v = p[i];
        if (v < 0 || v >= (long long)N) ok = 0;
    }
    g_is64 = ok;
}

__global__ void convert_edges_kernel(const void* ei_raw, int E) {
    int e = blockIdx.x * blockDim.x + threadIdx.x;
    if (e >= E) return;
    if (g_is64) {
        const long long* p = (const long long*)ei_raw;
        g_rows[e] = (int)p[e];
        g_cols[e] = (int)p[(size_t)E + e];
    } else {
        const int* p = (const int*)ei_raw;
        g_rows[e] = p[e];
        g_cols[e] = p[E + e];
    }
}

// ---------------------------------------------------------------------------
// degree / normalization
// ---------------------------------------------------------------------------
__global__ void zero_deg_kernel(float* deg, int N) {
    int i = blockIdx.x * blockDim.x + threadIdx.x;
    if (i < N) deg[i] = 0.0f;
}

__global__ void count_deg_kernel(float* deg, int E) {
    int e = blockIdx.x * blockDim.x + threadIdx.x;
    if (e < E) atomicAdd(&deg[g_cols[e]], 1.0f);
}

__global__ void finalize_dis_kernel(float* dis, int N) {
    int i = blockIdx.x * blockDim.x + threadIdx.x;
    if (i < N) dis[i] = rsqrtf(dis[i] + 1.0f);
}

__global__ void edge_norm_kernel(const float* __restrict__ dis, int E) {
    int e = blockIdx.x * blockDim.x + threadIdx.x;
    if (e < E) g_norm[e] = dis[g_rows[e]] * dis[g_cols[e]];
}

// ---------------------------------------------------------------------------
// Fused GEMM:  xw = act(A) @ W ;  agg = xw * dis[row]^2 + bias   (self-loop init)
// 128x128 tile, BK=8, 256 threads, 8x8 register tile per thread.
// ---------------------------------------------------------------------------
template <bool RELU_A>
__global__ __launch_bounds__(256)
void gemm_gcn_kernel(const float* __restrict__ A, const float* __restrict__ W,
                     const float* __restrict__ bias, const float* __restrict__ dis,
                     float* __restrict__ xw, float* __restrict__ agg,
                     int N, int K, int F)
{
    __shared__ float As[8][128];
    __shared__ float Bs[8][128];

    const int tid = threadIdx.x;
    const int bm = blockIdx.x, bn = blockIdx.y;
    const int tx = tid & 15, ty = tid >> 4;
    const int row0 = bm * 128 + ty * 8;
    const int col0 = bn * 128 + tx * 8;

    const int a_r = tid >> 1;           // 0..127
    const int a_k = (tid & 1) * 4;      // 0 or 4
    const int b_k = tid >> 5;           // 0..7
    const int b_c = (tid & 31) * 4;     // 0..124

    const int arow = bm * 128 + a_r;
    const bool avalid = (arow < N);
    const float* Arow = A + (size_t)arow * K;
    const float* Wbase = W + bn * 128 + b_c;

    float bj[8];
#pragma unroll
    for (int j = 0; j < 8; j++) bj[j] = bias[col0 + j];

    float acc[8][8];
#pragma unroll
    for (int i = 0; i < 8; i++)
#pragma unroll
        for (int j = 0; j < 8; j++) acc[i][j] = 0.0f;

    for (int k0 = 0; k0 < K; k0 += 8) {
        float4 av = make_float4(0.f, 0.f, 0.f, 0.f);
        if (avalid) av = *(const float4*)(Arow + k0 + a_k);
        if (RELU_A) {
            av.x = fmaxf(av.x, 0.f); av.y = fmaxf(av.y, 0.f);
            av.z = fmaxf(av.z, 0.f); av.w = fmaxf(av.w, 0.f);
        }
        As[a_k + 0][a_r] = av.x;
        As[a_k + 1][a_r] = av.y;
        As[a_k + 2][a_r] = av.z;
        As[a_k + 3][a_r] = av.w;

        float4 bv = *(const float4*)(Wbase + (size_t)(k0 + b_k) * F);
        *(float4*)&Bs[b_k][b_c] = bv;

        __syncthreads();
#pragma unroll
        for (int kk = 0; kk < 8; kk++) {
            float a[8], b[8];
            *(float4*)&a[0] = *(const float4*)&As[kk][ty * 8];
            *(float4*)&a[4] = *(const float4*)&As[kk][ty * 8 + 4];
            *(float4*)&b[0] = *(const float4*)&Bs[kk][tx * 8];
            *(float4*)&b[4] = *(const float4*)&Bs[kk][tx * 8 + 4];
#pragma unroll
            for (int i = 0; i < 8; i++)
#pragma unroll
                for (int j = 0; j < 8; j++) acc[i][j] += a[i] * b[j];
        }
        __syncthreads();
    }

#pragma unroll
    for (int i = 0; i < 8; i++) {
        int row = row0 + i;
        if (row < N) {
            float d = dis[row];
            float d2 = d * d;
            size_t base = (size_t)row * F + col0;
#pragma unroll
            for (int jq = 0; jq < 8; jq += 4) {
                float4 v = make_float4(acc[i][jq], acc[i][jq + 1], acc[i][jq + 2], acc[i][jq + 3]);
                *(float4*)(xw + base + jq) = v;
                float4 g = make_float4(v.x * d2 + bj[jq],
                                       v.y * d2 + bj[jq + 1],
                                       v.z * d2 + bj[jq + 2],
                                       v.w * d2 + bj[jq + 3]);
                *(float4*)(agg + base + jq) = g;
            }
        }
    }
}

// ---------------------------------------------------------------------------
// Edge aggregation: agg[col] += xw[row] * norm[e]
// One warp per edge, vectorized f32x4 global reductions.
// ---------------------------------------------------------------------------
template <int F>
__global__ __launch_bounds__(256)
void edge_agg_kernel(const float* __restrict__ xw, float* __restrict__ agg, int E)
{
    const int lane = threadIdx.x & 31;
    const int warp0 = (blockIdx.x * blockDim.x + threadIdx.x) >> 5;
    const int nw = (gridDim.x * blockDim.x) >> 5;

    for (int e = warp0; e < E; e += nw) {
        int r = g_rows[e];
        int c = g_cols[e];
        float nr = g_norm[e];

        const float4* src = (const float4*)(xw + (size_t)r * F);
        float4* dst = (float4*)(agg + (size_t)c * F);
#pragma unroll
        for (int j = lane; j < F / 4; j += 32) {
            float4 v = src[j];
            v.x *= nr; v.y *= nr; v.z *= nr; v.w *= nr;
            asm volatile("red.global.add.v4.f32 [%0], {%1,%2,%3,%4};"
                         :: "l"(dst + j), "f"(v.x), "f"(v.y), "f"(v.z), "f"(v.w)
                         : "memory");
        }
    }
}

// ---------------------------------------------------------------------------
// Heads
// ---------------------------------------------------------------------------
__global__ __launch_bounds__(256)
void head16_kernel(const float* __restrict__ A, const float* __restrict__ Wc,
                   const float* __restrict__ bc, float* __restrict__ out, int N)
{
    __shared__ float Ws[128 * 16];
    __shared__ float bs[16];
    for (int i = threadIdx.x; i < 128 * 16; i += 256) Ws[i] = Wc[i];
    if (threadIdx.x < 16) bs[threadIdx.x] = bc[threadIdx.x];
    __syncthreads();

    int j = threadIdx.x & 15;
    int rl = threadIdx.x >> 4;          // 16 rows per block
    int row = blockIdx.x * 16 + rl;
    if (row >= N) return;

    const float* a = A + (size_t)row * 128;
    float acc = 0.f;
#pragma unroll 8
    for (int k = 0; k < 128; k++) acc += a[k] * Ws[k * 16 + j];
    out[(size_t)row * 16 + j] = acc + bs[j];
}

__global__ __launch_bounds__(256)
void head2_sigmoid_kernel(const float* __restrict__ A, const float* __restrict__ Wt,
                          const float* __restrict__ bt, float* __restrict__ out, int N)
{
    __shared__ float Ws[128 * 2];
    __shared__ float bs[2];
    for (int i = threadIdx.x; i < 128 * 2; i += 256) Ws[i] = Wt[i];
    if (threadIdx.x < 2) bs[threadIdx.x] = bt[threadIdx.x];
    __syncthreads();

    int j = threadIdx.x & 1;
    int rl = threadIdx.x >> 1;          // 128 rows per block
    int row = blockIdx.x * 128 + rl;
    if (row >= N) return;

    const float* a = A + (size_t)row * 128;
    float acc = 0.f;
#pragma unroll 8
    for (int k = 0; k < 128; k++) acc += a[k] * Ws[k * 2 + j];
    float z = acc + bs[j];
    out[(size_t)row * 2 + j] = 1.0f / (1.0f + expf(-z));
}

// ---------------------------------------------------------------------------
// Launch
// ---------------------------------------------------------------------------
extern "C" void kernel_launch(void* const* d_in, const int* in_sizes, int n_in,
                              void* d_out, int out_size)
{
    const float* x = (const float*)d_in[0];
    const void* ei = d_in[1];
    const float* W1  = (const float*)d_in[2];
    const float* b1  = (const float*)d_in[3];
    const float* W2  = (const float*)d_in[4];
    const float* b2  = (const float*)d_in[5];
    const float* Wc  = (const float*)d_in[6];
    const float* bc  = (const float*)d_in[7];
    const float* We1 = (const float*)d_in[8];
    const float* be1 = (const float*)d_in[9];
    const float* We2 = (const float*)d_in[10];
    const float* be2 = (const float*)d_in[11];
    const float* We3 = (const float*)d_in[12];
    const float* be3 = (const float*)d_in[13];
    const float* We4 = (const float*)d_in[14];
    const float* be4 = (const float*)d_in[15];
    const float* Wt  = (const float*)d_in[16];
    const float* bt  = (const float*)d_in[17];
    float* out = (float*)d_out;

    const int N = in_sizes[0] / 128;
    const int E = in_sizes[1] / 2;

    float *dis, *xw, *h0, *h1;
    cudaGetSymbolAddress((void**)&dis, g_dis);
    cudaGetSymbolAddress((void**)&xw, g_xw);
    cudaGetSymbolAddress((void**)&h0, g_h0);
    cudaGetSymbolAddress((void**)&h1, g_h1);

    // --- edge index normalization ---
    detect_dtype_kernel<<<1, 1>>>(ei, N);
    convert_edges_kernel<<<(E + 255) / 256, 256>>>(ei, E);

    // --- degree / normalization ---
    zero_deg_kernel<<<(N + 255) / 256, 256>>>(dis, N);
    count_deg_kernel<<<(E + 255) / 256, 256>>>(dis, E);
    finalize_dis_kernel<<<(N + 255) / 256, 256>>>(dis, N);
    edge_norm_kernel<<<(E + 255) / 256, 256>>>(dis, E);

    dim3 gemm_grid_wide((N + 127) / 128, 2);   // F=256
    dim3 gemm_grid((N + 127) / 128, 1);        // F=128
    const int EDGE_BLOCKS = 2048;

    // --- classification branch ---
    gemm_gcn_kernel<false><<<gemm_grid_wide, 256>>>(x, W1, b1, dis, xw, h0, N, 128, 256);
    edge_agg_kernel<256><<<EDGE_BLOCKS, 256>>>(xw, h0, E);
    gemm_gcn_kernel<true><<<gemm_grid, 256>>>(h0, W2, b2, dis, xw, h1, N, 256, 128);
    edge_agg_kernel<128><<<EDGE_BLOCKS, 256>>>(xw, h1, E);
    head16_kernel<<<(N + 15) / 16, 256>>>(h1, Wc, bc, out, N);

    // --- encoder branch ---
    gemm_gcn_kernel<false><<<gemm_grid, 256>>>(x, We1, be1, dis, xw, h0, N, 128, 128);
    edge_agg_kernel<128><<<EDGE_BLOCKS, 256>>>(xw, h0, E);
    gemm_gcn_kernel<false><<<gemm_grid, 256>>>(h0, We2, be2, dis, xw, h1, N, 128, 128);
    edge_agg_kernel<128><<<EDGE_BLOCKS, 256>>>(xw, h1, E);
    gemm_gcn_kernel<false><<<gemm_grid, 256>>>(h1, We3, be3, dis, xw, h0, N, 128, 128);
    edge_agg_kernel<128><<<EDGE_BLOCKS, 256>>>(xw, h0, E);
    gemm_gcn_kernel<false><<<gemm_grid, 256>>>(h0, We4, be4, dis, xw, h1, N, 128, 128);
    edge_agg_kernel<128><<<EDGE_BLOCKS, 256>>>(xw, h1, E);
    head2_sigmoid_kernel<<<(N + 127) / 128, 256>>>(h1, Wt, bt, out + (size_t)N * 16, N);
}

// round 3
// speedup vs baseline: 1.4703x; 1.4703x over previous
#include <cuda_runtime.h>
#include <math.h>

#define NNODES 100000
#define NEDGES 1600000
#define MAXF 256
#define SCAN_BS 256

// Scratch (device globals; allocation-free per harness rules)
__device__ float g_dis[NNODES];
__device__ float g_xw[(size_t)NNODES * MAXF];
__device__ float g_h0[(size_t)NNODES * MAXF];
__device__ float g_h1[(size_t)NNODES * MAXF];
__device__ int   g_rows[NEDGES];
__device__ int   g_cols[NEDGES];
__device__ int   g_cnt[NNODES];
__device__ int   g_cur[NNODES];
__device__ int   g_rowptr[NNODES + 1];
__device__ int   g_btot[(NNODES + SCAN_BS - 1) / SCAN_BS + 1];
__device__ int   g_boff[(NNODES + SCAN_BS - 1) / SCAN_BS + 1];
__device__ int   g_csr_src[NEDGES];
__device__ float g_csr_norm[NEDGES];
__device__ int   g_is64;

// ---------------------------------------------------------------------------
// Edge-index dtype detection
// ---------------------------------------------------------------------------
__global__ void detect_dtype_kernel(const void* ei_raw, int N) {
    const long long* p = (const long long*)ei_raw;
    int ok = 1;
    for (int i = 0; i < 8; i++) {
        long long v = p[i];
        if (v < 0 || v >= (long long)N) ok = 0;
    }
    g_is64 = ok;
}

__global__ void zero_kernel(int N) {
    int i = blockIdx.x * blockDim.x + threadIdx.x;
    if (i < N) { g_cnt[i] = 0; g_cur[i] = 0; }
}

// convert edges to int32 arrays + count in-degree
__global__ void convert_count_kernel(const void* ei_raw, int E) {
    int e = blockIdx.x * blockDim.x + threadIdx.x;
    if (e >= E) return;
    int r, c;
    if (g_is64) {
        const long long* p = (const long long*)ei_raw;
        r = (int)p[e];
        c = (int)p[(size_t)E + e];
    } else {
        const int* p = (const int*)ei_raw;
        r = p[e];
        c = p[E + e];
    }
    g_rows[e] = r;
    g_cols[e] = c;
    atomicAdd(&g_cnt[c], 1);
}

// ---------------------------------------------------------------------------
// Exclusive scan of g_cnt -> g_rowptr (3 kernels)
// ---------------------------------------------------------------------------
__global__ void scan_blocks_kernel(int N) {
    __shared__ int s[SCAN_BS];
    int i = blockIdx.x * SCAN_BS + threadIdx.x;
    int v = (i < N) ? g_cnt[i] : 0;
    s[threadIdx.x] = v;
    __syncthreads();
    // Hillis-Steele inclusive scan
    for (int off = 1; off < SCAN_BS; off <<= 1) {
        int t = (threadIdx.x >= off) ? s[threadIdx.x - off] : 0;
        __syncthreads();
        s[threadIdx.x] += t;
        __syncthreads();
    }
    if (i < N) g_rowptr[i] = s[threadIdx.x] - v;   // exclusive
    if (threadIdx.x == SCAN_BS - 1) g_btot[blockIdx.x] = s[SCAN_BS - 1];
}

__global__ void scan_tops_kernel(int nblocks) {
    __shared__ int s[512];
    int v = (threadIdx.x < nblocks) ? g_btot[threadIdx.x] : 0;
    s[threadIdx.x] = v;
    __syncthreads();
    for (int off = 1; off < 512; off <<= 1) {
        int t = (threadIdx.x >= off) ? s[threadIdx.x - off] : 0;
        __syncthreads();
        s[threadIdx.x] += t;
        __syncthreads();
    }
    if (threadIdx.x < nblocks) g_boff[threadIdx.x] = s[threadIdx.x] - v;  // exclusive
}

__global__ void scan_add_kernel(int N, int E) {
    int i = blockIdx.x * SCAN_BS + threadIdx.x;
    if (i < N) g_rowptr[i] += g_boff[blockIdx.x];
    if (i == 0) g_rowptr[N] = E;
}

__global__ void finalize_dis_kernel(int N) {
    int i = blockIdx.x * blockDim.x + threadIdx.x;
    if (i < N) g_dis[i] = rsqrtf((float)g_cnt[i] + 1.0f);
}

// Fill CSR: csr entries grouped by destination (col)
__global__ void fill_csr_kernel(int E) {
    int e = blockIdx.x * blockDim.x + threadIdx.x;
    if (e >= E) return;
    int r = g_rows[e];
    int c = g_cols[e];
    int pos = g_rowptr[c] + atomicAdd(&g_cur[c], 1);
    g_csr_src[pos] = r;
    g_csr_norm[pos] = g_dis[r] * g_dis[c];
}

// ---------------------------------------------------------------------------
// Fused GEMM:  xw = act(A) @ W ;  agg = xw * dis[row]^2 + bias   (self-loop init)
// ---------------------------------------------------------------------------
template <bool RELU_A>
__global__ __launch_bounds__(256)
void gemm_gcn_kernel(const float* __restrict__ A, const float* __restrict__ W,
                     const float* __restrict__ bias, const float* __restrict__ dis,
                     float* __restrict__ xw, float* __restrict__ agg,
                     int N, int K, int F)
{
    __shared__ float As[8][128];
    __shared__ float Bs[8][128];

    const int tid = threadIdx.x;
    const int bm = blockIdx.x, bn = blockIdx.y;
    const int tx = tid & 15, ty = tid >> 4;
    const int row0 = bm * 128 + ty * 8;
    const int col0 = bn * 128 + tx * 8;

    const int a_r = tid >> 1;
    const int a_k = (tid & 1) * 4;
    const int b_k = tid >> 5;
    const int b_c = (tid & 31) * 4;

    const int arow = bm * 128 + a_r;
    const bool avalid = (arow < N);
    const float* Arow = A + (size_t)arow * K;
    const float* Wbase = W + bn * 128 + b_c;

    float bj[8];
#pragma unroll
    for (int j = 0; j < 8; j++) bj[j] = bias[col0 + j];

    float acc[8][8];
#pragma unroll
    for (int i = 0; i < 8; i++)
#pragma unroll
        for (int j = 0; j < 8; j++) acc[i][j] = 0.0f;

    for (int k0 = 0; k0 < K; k0 += 8) {
        float4 av = make_float4(0.f, 0.f, 0.f, 0.f);
        if (avalid) av = *(const float4*)(Arow + k0 + a_k);
        if (RELU_A) {
            av.x = fmaxf(av.x, 0.f); av.y = fmaxf(av.y, 0.f);
            av.z = fmaxf(av.z, 0.f); av.w = fmaxf(av.w, 0.f);
        }
        As[a_k + 0][a_r] = av.x;
        As[a_k + 1][a_r] = av.y;
        As[a_k + 2][a_r] = av.z;
        As[a_k + 3][a_r] = av.w;

        float4 bv = *(const float4*)(Wbase + (size_t)(k0 + b_k) * F);
        *(float4*)&Bs[b_k][b_c] = bv;

        __syncthreads();
#pragma unroll
        for (int kk = 0; kk < 8; kk++) {
            float a[8], b[8];
            *(float4*)&a[0] = *(const float4*)&As[kk][ty * 8];
            *(float4*)&a[4] = *(const float4*)&As[kk][ty * 8 + 4];
            *(float4*)&b[0] = *(const float4*)&Bs[kk][tx * 8];
            *(float4*)&b[4] = *(const float4*)&Bs[kk][tx * 8 + 4];
#pragma unroll
            for (int i = 0; i < 8; i++)
#pragma unroll
                for (int j = 0; j < 8; j++) acc[i][j] += a[i] * b[j];
        }
        __syncthreads();
    }

#pragma unroll
    for (int i = 0; i < 8; i++) {
        int row = row0 + i;
        if (row < N) {
            float d = dis[row];
            float d2 = d * d;
            size_t base = (size_t)row * F + col0;
#pragma unroll
            for (int jq = 0; jq < 8; jq += 4) {
                float4 v = make_float4(acc[i][jq], acc[i][jq + 1], acc[i][jq + 2], acc[i][jq + 3]);
                *(float4*)(xw + base + jq) = v;
                float4 g = make_float4(v.x * d2 + bj[jq],
                                       v.y * d2 + bj[jq + 1],
                                       v.z * d2 + bj[jq + 2],
                                       v.w * d2 + bj[jq + 3]);
                *(float4*)(agg + base + jq) = g;
            }
        }
    }
}

// ---------------------------------------------------------------------------
// CSR gather-side aggregation: agg[c] += sum_{e in in(c)} norm[e] * xw[src[e]]
// One warp per destination node; accumulate in registers, no atomics.
// ---------------------------------------------------------------------------
template <int F>
__global__ __launch_bounds__(256)
void csr_agg_kernel(const float* __restrict__ xw, float* __restrict__ agg, int N)
{
    const int lane = threadIdx.x & 31;
    const int node = (blockIdx.x * blockDim.x + threadIdx.x) >> 5;
    if (node >= N) return;

    int beg = g_rowptr[node];
    int end = g_rowptr[node + 1];
    if (beg == end) return;   // self-loop term already written by GEMM

    constexpr int NV = F / 128;     // float4s per lane (1 for F=128, 2 for F=256)
    float4 acc[NV];
#pragma unroll
    for (int q = 0; q < NV; q++) acc[q] = make_float4(0.f, 0.f, 0.f, 0.f);

    for (int base = beg; base < end; base += 32) {
        int n = min(32, end - base);
        int srcReg = 0; float nrReg = 0.f;
        if (lane < n) {
            srcReg = g_csr_src[base + lane];
            nrReg  = g_csr_norm[base + lane];
        }
        for (int k = 0; k < n; k++) {
            int   r = __shfl_sync(0xffffffffu, srcReg, k);
            float w = __shfl_sync(0xffffffffu, nrReg, k);
            const float4* s = (const float4*)(xw + (size_t)r * F);
#pragma unroll
            for (int q = 0; q < NV; q++) {
                float4 v = s[lane + q * 32];
                acc[q].x += w * v.x;
                acc[q].y += w * v.y;
                acc[q].z += w * v.z;
                acc[q].w += w * v.w;
            }
        }
    }

    float4* d = (float4*)(agg + (size_t)node * F);
#pragma unroll
    for (int q = 0; q < NV; q++) {
        float4 cur = d[lane + q * 32];
        cur.x += acc[q].x; cur.y += acc[q].y;
        cur.z += acc[q].z; cur.w += acc[q].w;
        d[lane + q * 32] = cur;
    }
}

// ---------------------------------------------------------------------------
// Heads
// ---------------------------------------------------------------------------
__global__ __launch_bounds__(256)
void head16_kernel(const float* __restrict__ A, const float* __restrict__ Wc,
                   const float* __restrict__ bc, float* __restrict__ out, int N)
{
    __shared__ float Ws[128 * 16];
    __shared__ float bs[16];
    for (int i = threadIdx.x; i < 128 * 16; i += 256) Ws[i] = Wc[i];
    if (threadIdx.x < 16) bs[threadIdx.x] = bc[threadIdx.x];
    __syncthreads();

    int j = threadIdx.x & 15;
    int rl = threadIdx.x >> 4;
    int row = blockIdx.x * 16 + rl;
    if (row >= N) return;

    const float* a = A + (size_t)row * 128;
    float acc = 0.f;
#pragma unroll 8
    for (int k = 0; k < 128; k++) acc += a[k] * Ws[k * 16 + j];
    out[(size_t)row * 16 + j] = acc + bs[j];
}

__global__ __launch_bounds__(256)
void head2_sigmoid_kernel(const float* __restrict__ A, const float* __restrict__ Wt,
                          const float* __restrict__ bt, float* __restrict__ out, int N)
{
    __shared__ float Ws[128 * 2];
    __shared__ float bs[2];
    for (int i = threadIdx.x; i < 128 * 2; i += 256) Ws[i] = Wt[i];
    if (threadIdx.x < 2) bs[threadIdx.x] = bt[threadIdx.x];
    __syncthreads();

    int j = threadIdx.x & 1;
    int rl = threadIdx.x >> 1;
    int row = blockIdx.x * 128 + rl;
    if (row >= N) return;

    const float* a = A + (size_t)row * 128;
    float acc = 0.f;
#pragma unroll 8
    for (int k = 0; k < 128; k++) acc += a[k] * Ws[k * 2 + j];
    float z = acc + bs[j];
    out[(size_t)row * 2 + j] = 1.0f / (1.0f + expf(-z));
}

// ---------------------------------------------------------------------------
// Launch
// ---------------------------------------------------------------------------
extern "C" void kernel_launch(void* const* d_in, const int* in_sizes, int n_in,
                              void* d_out, int out_size)
{
    const float* x = (const float*)d_in[0];
    const void* ei = d_in[1];
    const float* W1  = (const float*)d_in[2];
    const float* b1  = (const float*)d_in[3];
    const float* W2  = (const float*)d_in[4];
    const float* b2  = (const float*)d_in[5];
    const float* Wc  = (const float*)d_in[6];
    const float* bc  = (const float*)d_in[7];
    const float* We1 = (const float*)d_in[8];
    const float* be1 = (const float*)d_in[9];
    const float* We2 = (const float*)d_in[10];
    const float* be2 = (const float*)d_in[11];
    const float* We3 = (const float*)d_in[12];
    const float* be3 = (const float*)d_in[13];
    const float* We4 = (const float*)d_in[14];
    const float* be4 = (const float*)d_in[15];
    const float* Wt  = (const float*)d_in[16];
    const float* bt  = (const float*)d_in[17];
    float* out = (float*)d_out;

    const int N = in_sizes[0] / 128;
    const int E = in_sizes[1] / 2;
    const int nscan = (N + SCAN_BS - 1) / SCAN_BS;

    float *dis, *xw, *h0, *h1;
    cudaGetSymbolAddress((void**)&dis, g_dis);
    cudaGetSymbolAddress((void**)&xw, g_xw);
    cudaGetSymbolAddress((void**)&h0, g_h0);
    cudaGetSymbolAddress((void**)&h1, g_h1);

    // --- preprocessing: dtype, degrees, scan, CSR, norms ---
    detect_dtype_kernel<<<1, 1>>>(ei, N);
    zero_kernel<<<(N + 255) / 256, 256>>>(N);
    convert_count_kernel<<<(E + 255) / 256, 256>>>(ei, E);
    scan_blocks_kernel<<<nscan, SCAN_BS>>>(N);
    scan_tops_kernel<<<1, 512>>>(nscan);
    scan_add_kernel<<<nscan, SCAN_BS>>>(N, E);
    finalize_dis_kernel<<<(N + 255) / 256, 256>>>(N);
    fill_csr_kernel<<<(E + 255) / 256, 256>>>(E);

    dim3 gemm_grid_wide((N + 127) / 128, 2);   // F=256
    dim3 gemm_grid((N + 127) / 128, 1);        // F=128
    const int AGG_BLOCKS = (N + 7) / 8;        // 8 warps per 256-thread block

    // --- classification branch ---
    gemm_gcn_kernel<false><<<gemm_grid_wide, 256>>>(x, W1, b1, dis, xw, h0, N, 128, 256);
    csr_agg_kernel<256><<<AGG_BLOCKS, 256>>>(xw, h0, N);
    gemm_gcn_kernel<true><<<gemm_grid, 256>>>(h0, W2, b2, dis, xw, h1, N, 256, 128);
    csr_agg_kernel<128><<<AGG_BLOCKS, 256>>>(xw, h1, N);
    head16_kernel<<<(N + 15) / 16, 256>>>(h1, Wc, bc, out, N);

    // --- encoder branch ---
    gemm_gcn_kernel<false><<<gemm_grid, 256>>>(x, We1, be1, dis, xw, h0, N, 128, 128);
    csr_agg_kernel<128><<<AGG_BLOCKS, 256>>>(xw, h0, N);
    gemm_gcn_kernel<false><<<gemm_grid, 256>>>(h0, We2, be2, dis, xw, h1, N, 128, 128);
    csr_agg_kernel<128><<<AGG_BLOCKS, 256>>>(xw, h1, N);
    gemm_gcn_kernel<false><<<gemm_grid, 256>>>(h1, We3, be3, dis, xw, h0, N, 128, 128);
    csr_agg_kernel<128><<<AGG_BLOCKS, 256>>>(xw, h0, N);
    gemm_gcn_kernel<false><<<gemm_grid, 256>>>(h0, We4, be4, dis, xw, h1, N, 128, 128);
    csr_agg_kernel<128><<<AGG_BLOCKS, 256>>>(xw, h1, N);
    head2_sigmoid_kernel<<<(N + 127) / 128, 256>>>(h1, Wt, bt, out + (size_t)N * 16, N);
}